// round 12
// baseline (speedup 1.0000x reference)
#include <cuda_runtime.h>

typedef unsigned long long u64;
typedef unsigned int u32;

constexpr int NB = 32, NC = 64, NH = 112, NW = 112;
constexpr int HW = NH * NW;               // 12544
constexpr int SEGROW4 = NW / 4;           // 28 (pack kernel, 4 px/thread)
constexpr int NSEG4 = NB * NH * SEGROW4;  // 100352
constexpr int SEGROW2 = NW / 2;           // 56 (conv kernels, 2 px/thread)
constexpr int NSEG2 = NB * NH * SEGROW2;  // 200704
constexpr int TPB = 128;
constexpr int NBLK4 = NSEG4 / TPB;        // 784
constexpr int NBLK2 = NSEG2 / TPB;        // 1568
constexpr float kALPHA = 0.25f;

// scratch (static device globals; no dynamic allocation)
__device__ u64 g_bits1[NB * HW];
__device__ u64 g_bits2[NB * HW];
__device__ float g_out1[(size_t)NB * NC * HW];
__device__ u64 g_wb[2][NC][9];
__device__ int g_corr[2][NC][9];
__device__ float g_scale[2][NC];

// ---------------------------------------------------------------------------
// Weight prep: scale[o]=mean|w|, bit-packed sign words, zero-pad corrections.
// ---------------------------------------------------------------------------
__global__ void prep_weights_kernel(const float* __restrict__ w3,
                                    const float* __restrict__ wpw) {
    int o = blockIdx.x;
    int cv = blockIdx.y;
    const float* w = cv ? wpw : w3;
    int i = threadIdx.x;
    int lane = i & 31, warp = i >> 5;
    const float* wrow = w + (size_t)(o * NC + i) * 9;
    float wv[9];
    float s = 0.f;
#pragma unroll
    for (int t = 0; t < 9; t++) { wv[t] = wrow[t]; s += fabsf(wv[t]); }
    __shared__ u32 sb[2][9];
#pragma unroll
    for (int t = 0; t < 9; t++) {
        u32 m = __ballot_sync(0xffffffffu, wv[t] >= 0.f);
        if (lane == 0) sb[warp][t] = m;
    }
#pragma unroll
    for (int off = 16; off > 0; off >>= 1)
        s += __shfl_down_sync(0xffffffffu, s, off);
    __shared__ float ssum[2];
    if (lane == 0) ssum[warp] = s;
    __syncthreads();
    if (i == 0) g_scale[cv][o] = (ssum[0] + ssum[1]) * (1.0f / 576.0f);
    if (i < 9) {
        u64 wb = ((u64)sb[1][i] << 32) | (u64)sb[0][i];
        g_wb[cv][o][i] = wb;
        g_corr[cv][o][i] = 64 - 2 * __popcll(wb);
    }
}

// ---------------------------------------------------------------------------
// Pack sign(x + b11) into 64-bit channel words. Thread = 4 consecutive pixels.
// ---------------------------------------------------------------------------
__global__ void __launch_bounds__(TPB)
pack_input_kernel(const float* __restrict__ x, const float* __restrict__ b11) {
    __shared__ float sb[NC];
    int tid = threadIdx.x;
    if (tid < NC) sb[tid] = b11[tid];
    __syncthreads();
    int seg = blockIdx.x * TPB + tid;
    int b = seg / (NH * SEGROW4);
    int r = seg % (NH * SEGROW4);
    int y = r / SEGROW4;
    int sx = (r % SEGROW4) * 4;
    const float* xp = x + (size_t)b * NC * HW + y * NW + sx;
    u32 lo0 = 0, lo1 = 0, lo2 = 0, lo3 = 0;
    u32 hi0 = 0, hi1 = 0, hi2 = 0, hi3 = 0;
#pragma unroll
    for (int c = 0; c < 32; c++) {
        float4 v = *(const float4*)(xp + (size_t)c * HW);
        float bb = sb[c];
        u32 bit = 1u << c;
        if (v.x + bb >= 0.f) lo0 |= bit;
        if (v.y + bb >= 0.f) lo1 |= bit;
        if (v.z + bb >= 0.f) lo2 |= bit;
        if (v.w + bb >= 0.f) lo3 |= bit;
    }
#pragma unroll
    for (int c = 32; c < 64; c++) {
        float4 v = *(const float4*)(xp + (size_t)c * HW);
        float bb = sb[c];
        u32 bit = 1u << (c - 32);
        if (v.x + bb >= 0.f) hi0 |= bit;
        if (v.y + bb >= 0.f) hi1 |= bit;
        if (v.z + bb >= 0.f) hi2 |= bit;
        if (v.w + bb >= 0.f) hi3 |= bit;
    }
    u64* op = g_bits1 + (size_t)b * HW + y * NW + sx;
    ulonglong2* ov = (ulonglong2*)op;
    ov[0] = make_ulonglong2(((u64)hi0 << 32) | lo0, ((u64)hi1 << 32) | lo1);
    ov[1] = make_ulonglong2(((u64)hi2 << 32) | lo2, ((u64)hi3 << 32) | lo3);
}

// ---------------------------------------------------------------------------
// Binary 3x3 conv via XOR+POPC, fully fused epilogue.
// Thread = 2 consecutive pixels x all 64 output channels, processed as
// channel-pairs. Loop unrolled 2 pairs with a static 2-slot residual ring
// (prefetch distance = 2 pair-computes, MLP up to 4).
// Weight rows read as LDS.128 (80B padded rows), epilogue scalars as float4.
// CV==0: out1 = prelu(x + a*conv + b12, a1) + b13 -> g_out1, bitpack -> g_bits2
// CV==1: out2 = prelu(a*conv + out1 + b22, a2) + b23 -> dout
// ---------------------------------------------------------------------------
template <int CV>
__global__ void __launch_bounds__(TPB)
bconv_kernel(const float* __restrict__ xin, float* __restrict__ dout,
             const float* __restrict__ bA, const float* __restrict__ sl_,
             const float* __restrict__ bB, const float* __restrict__ bS) {
    __shared__ u64 s_wb[NC][10];      // 80B rows: 16B-aligned per row
    __shared__ int s_corr[NC][9];
    __shared__ float4 s_ep[NC];       // (alpha*scale, bA, slope, bB)
    __shared__ float s_bS[NC];
    int tid = threadIdx.x;
    for (int k = tid; k < NC * 9; k += TPB) {
        int o = k / 9, t = k - o * 9;
        s_wb[o][t] = g_wb[CV][o][t];
        s_corr[o][t] = g_corr[CV][o][t];
    }
    if (tid < NC) {
        s_ep[tid] = make_float4(g_scale[CV][tid] * kALPHA, bA[tid], sl_[tid], bB[tid]);
        s_bS[tid] = (CV == 0) ? bS[tid] : 0.f;
    }
    __syncthreads();

    int seg = blockIdx.x * TPB + tid;
    int b = seg / (NH * SEGROW2);
    int r = seg % (NH * SEGROW2);
    int y = r / SEGROW2;
    int sx = (r % SEGROW2) * 2;
    bool top = (y == 0), bot = (y == NH - 1);
    bool left = (sx == 0), right = (sx + 2 == NW);
    bool border = top | bot | left | right;

    const u64* bitsIn = (CV == 0) ? g_bits1 : g_bits2;
    const float* resid = (CV == 0) ? xin : g_out1;
    float* outp = (CV == 0) ? g_out1 : dout;

    // activation bit patch: 3 rows x 4 cols covers 2 output pixels; OOB -> 0
    const u64* bp = bitsIn + (size_t)b * HW;
    u64 a[3][4];
#pragma unroll
    for (int rr = 0; rr < 3; rr++) {
        int yy = y - 1 + rr;
        bool rv = (yy >= 0) && (yy < NH);
#pragma unroll
        for (int k = 0; k < 4; k++) {
            int cx = sx - 1 + k;
            a[rr][k] = (rv && cx >= 0 && cx < NW) ? __ldg(bp + yy * NW + cx) : 0ull;
        }
    }

    size_t pixbase = (size_t)b * NC * HW + (size_t)(y * NW + sx);
    const float* rp = resid + pixbase;
    float* op = outp + pixbase;

    u32 slo0 = 0, slo1 = 0, shi0 = 0, shi1 = 0;

    // process one channel-pair (o, o+1) with residuals resA/resB
    auto do_pair = [&](int o, float2 resA, float2 resB) {
        // weight rows: 5x LDS.128 each (last vector reads the pad word)
        const ulonglong2* wpA = (const ulonglong2*)&s_wb[o][0];
        const ulonglong2* wpB = (const ulonglong2*)&s_wb[o + 1][0];
        u64 wA[9], wB[9];
        {
            ulonglong2 t0 = wpA[0], t1 = wpA[1], t2 = wpA[2], t3 = wpA[3], t4 = wpA[4];
            wA[0] = t0.x; wA[1] = t0.y; wA[2] = t1.x; wA[3] = t1.y;
            wA[4] = t2.x; wA[5] = t2.y; wA[6] = t3.x; wA[7] = t3.y; wA[8] = t4.x;
        }
        {
            ulonglong2 t0 = wpB[0], t1 = wpB[1], t2 = wpB[2], t3 = wpB[3], t4 = wpB[4];
            wB[0] = t0.x; wB[1] = t0.y; wB[2] = t1.x; wB[3] = t1.y;
            wB[4] = t2.x; wB[5] = t2.y; wB[6] = t3.x; wB[7] = t3.y; wB[8] = t4.x;
        }
        int p0 = 0, p1 = 0, q0 = 0, q1 = 0;
#pragma unroll
        for (int t = 0; t < 9; t++) {
            int rr = t / 3, cc = t - rr * 3;
            u64 a0 = a[rr][cc + 0];
            u64 a1 = a[rr][cc + 1];
            p0 += __popcll(wA[t] ^ a0);
            p1 += __popcll(wA[t] ^ a1);
            q0 += __popcll(wB[t] ^ a0);
            q1 += __popcll(wB[t] ^ a1);
        }
        int cbA = 0, clA = 0, crA = 0, cbB = 0, clB = 0, crB = 0;
        if (border) {
            const int* cA = s_corr[o];
            const int* cB = s_corr[o + 1];
            if (top)  { cbA += cA[0] + cA[1] + cA[2]; cbB += cB[0] + cB[1] + cB[2]; }
            if (bot)  { cbA += cA[6] + cA[7] + cA[8]; cbB += cB[6] + cB[7] + cB[8]; }
            if (left) {
                clA = cA[3] + (top ? 0 : cA[0]) + (bot ? 0 : cA[6]);
                clB = cB[3] + (top ? 0 : cB[0]) + (bot ? 0 : cB[6]);
            }
            if (right) {
                crA = cA[5] + (top ? 0 : cA[2]) + (bot ? 0 : cA[8]);
                crB = cB[5] + (top ? 0 : cB[2]) + (bot ? 0 : cB[8]);
            }
        }
        // channel o
        {
            float4 ep = s_ep[o];
            float v0 = fmaf(ep.x, (float)(576 - 2 * p0 - cbA - clA), resA.x);
            float v1 = fmaf(ep.x, (float)(576 - 2 * p1 - cbA - crA), resA.y);
            v0 += ep.y; v1 += ep.y;
            v0 = fmaxf(v0, 0.f) + ep.z * fminf(v0, 0.f);
            v1 = fmaxf(v1, 0.f) + ep.z * fminf(v1, 0.f);
            v0 += ep.w; v1 += ep.w;
            *(float2*)(op + (size_t)o * HW) = make_float2(v0, v1);
            if (CV == 0) {
                float bs = s_bS[o];
                u32 bit = 1u << (o & 31);
                if (o < 32) {
                    if (v0 + bs >= 0.f) slo0 |= bit;
                    if (v1 + bs >= 0.f) slo1 |= bit;
                } else {
                    if (v0 + bs >= 0.f) shi0 |= bit;
                    if (v1 + bs >= 0.f) shi1 |= bit;
                }
            }
        }
        // channel o+1
        {
            int o1 = o + 1;
            float4 ep = s_ep[o1];
            float v0 = fmaf(ep.x, (float)(576 - 2 * q0 - cbB - clB), resB.x);
            float v1 = fmaf(ep.x, (float)(576 - 2 * q1 - cbB - crB), resB.y);
            v0 += ep.y; v1 += ep.y;
            v0 = fmaxf(v0, 0.f) + ep.z * fminf(v0, 0.f);
            v1 = fmaxf(v1, 0.f) + ep.z * fminf(v1, 0.f);
            v0 += ep.w; v1 += ep.w;
            *(float2*)(op + (size_t)o1 * HW) = make_float2(v0, v1);
            if (CV == 0) {
                float bs = s_bS[o1];
                u32 bit = 1u << (o1 & 31);
                if (o1 < 32) {
                    if (v0 + bs >= 0.f) slo0 |= bit;
                    if (v1 + bs >= 0.f) slo1 |= bit;
                } else {
                    if (v0 + bs >= 0.f) shi0 |= bit;
                    if (v1 + bs >= 0.f) shi1 |= bit;
                }
            }
        }
    };

    // static 2-slot residual ring, prefetch distance = 2 pairs (4 channels)
    float2 rA0 = *(const float2*)(rp);
    float2 rB0 = *(const float2*)(rp + HW);
    float2 rA1 = *(const float2*)(rp + 2 * (size_t)HW);
    float2 rB1 = *(const float2*)(rp + 3 * (size_t)HW);

#pragma unroll 1
    for (int o = 0; o < NC; o += 4) {
        // pair o: consume slot 0, refill with pair o+4
        float2 cA = rA0, cB = rB0;
        int n0 = (o + 4 < NC) ? o + 4 : NC - 2;
        rA0 = *(const float2*)(rp + (size_t)n0 * HW);
        rB0 = *(const float2*)(rp + (size_t)(n0 + 1) * HW);
        do_pair(o, cA, cB);

        // pair o+2: consume slot 1, refill with pair o+6
        cA = rA1; cB = rB1;
        int n1 = (o + 6 < NC) ? o + 6 : NC - 2;
        rA1 = *(const float2*)(rp + (size_t)n1 * HW);
        rB1 = *(const float2*)(rp + (size_t)(n1 + 1) * HW);
        do_pair(o + 2, cA, cB);
    }

    if (CV == 0) {
        u64* obp = g_bits2 + (size_t)b * HW + y * NW + sx;
        *(ulonglong2*)obp =
            make_ulonglong2(((u64)shi0 << 32) | slo0, ((u64)shi1 << 32) | slo1);
    }
}

extern "C" void kernel_launch(void* const* d_in, const int* in_sizes, int n_in,
                              void* d_out, int out_size) {
    const float* x   = (const float*)d_in[0];
    const float* w3  = (const float*)d_in[1];
    const float* wpw = (const float*)d_in[2];
    const float* b11 = (const float*)d_in[3];
    const float* b12 = (const float*)d_in[4];
    const float* b13 = (const float*)d_in[5];
    const float* b21 = (const float*)d_in[6];
    const float* b22 = (const float*)d_in[7];
    const float* b23 = (const float*)d_in[8];
    const float* a1  = (const float*)d_in[9];
    const float* a2  = (const float*)d_in[10];
    float* out = (float*)d_out;

    prep_weights_kernel<<<dim3(64, 2), 64>>>(w3, wpw);
    pack_input_kernel<<<NBLK4, TPB>>>(x, b11);
    bconv_kernel<0><<<NBLK2, TPB>>>(x, nullptr, b12, a1, b13, b21);
    bconv_kernel<1><<<NBLK2, TPB>>>(nullptr, out, b22, a2, b23, nullptr);
}

// round 15
// speedup vs baseline: 1.0005x; 1.0005x over previous
#include <cuda_runtime.h>
#include <cuda_fp16.h>

typedef unsigned long long u64;
typedef unsigned int u32;

constexpr int NB = 32, NC = 64, NH = 112, NW = 112;
constexpr int HW = NH * NW;               // 12544
constexpr int SEGROW4 = NW / 4;           // 28 (pack kernel, 4 px/thread)
constexpr int NSEG4 = NB * NH * SEGROW4;  // 100352
constexpr int SEGROW2 = NW / 2;           // 56 (conv kernels, 2 px/thread)
constexpr int NSEG2 = NB * NH * SEGROW2;  // 200704
constexpr int TPB = 128;
constexpr int NBLK4 = NSEG4 / TPB;        // 784
constexpr int NBLK2 = NSEG2 / TPB;        // 1568
constexpr float kALPHA = 0.25f;

// scratch (static device globals; no dynamic allocation)
__device__ u64 g_bits1[NB * HW];
__device__ u64 g_bits2[NB * HW];
__device__ __half g_out1[(size_t)NB * NC * HW];   // fp16: 51.5 MB, L2-resident
__device__ u64 g_wb[2][NC][9];
__device__ int g_corr[2][NC][9];
__device__ float g_scale[2][NC];

// ---------------------------------------------------------------------------
// Weight prep: scale[o]=mean|w|, bit-packed sign words, zero-pad corrections.
// ---------------------------------------------------------------------------
__global__ void prep_weights_kernel(const float* __restrict__ w3,
                                    const float* __restrict__ wpw) {
    int o = blockIdx.x;
    int cv = blockIdx.y;
    const float* w = cv ? wpw : w3;
    int i = threadIdx.x;
    int lane = i & 31, warp = i >> 5;
    const float* wrow = w + (size_t)(o * NC + i) * 9;
    float wv[9];
    float s = 0.f;
#pragma unroll
    for (int t = 0; t < 9; t++) { wv[t] = wrow[t]; s += fabsf(wv[t]); }
    __shared__ u32 sb[2][9];
#pragma unroll
    for (int t = 0; t < 9; t++) {
        u32 m = __ballot_sync(0xffffffffu, wv[t] >= 0.f);
        if (lane == 0) sb[warp][t] = m;
    }
#pragma unroll
    for (int off = 16; off > 0; off >>= 1)
        s += __shfl_down_sync(0xffffffffu, s, off);
    __shared__ float ssum[2];
    if (lane == 0) ssum[warp] = s;
    __syncthreads();
    if (i == 0) g_scale[cv][o] = (ssum[0] + ssum[1]) * (1.0f / 576.0f);
    if (i < 9) {
        u64 wb = ((u64)sb[1][i] << 32) | (u64)sb[0][i];
        g_wb[cv][o][i] = wb;
        g_corr[cv][o][i] = 64 - 2 * __popcll(wb);
    }
}

// ---------------------------------------------------------------------------
// Pack sign(x + b11) into 64-bit channel words. Thread = 4 consecutive pixels.
// ---------------------------------------------------------------------------
__global__ void __launch_bounds__(TPB)
pack_input_kernel(const float* __restrict__ x, const float* __restrict__ b11) {
    __shared__ float sb[NC];
    int tid = threadIdx.x;
    if (tid < NC) sb[tid] = b11[tid];
    __syncthreads();
    int seg = blockIdx.x * TPB + tid;
    int b = seg / (NH * SEGROW4);
    int r = seg % (NH * SEGROW4);
    int y = r / SEGROW4;
    int sx = (r % SEGROW4) * 4;
    const float* xp = x + (size_t)b * NC * HW + y * NW + sx;
    u32 lo0 = 0, lo1 = 0, lo2 = 0, lo3 = 0;
    u32 hi0 = 0, hi1 = 0, hi2 = 0, hi3 = 0;
#pragma unroll
    for (int c = 0; c < 32; c++) {
        float4 v = *(const float4*)(xp + (size_t)c * HW);
        float bb = sb[c];
        u32 bit = 1u << c;
        if (v.x + bb >= 0.f) lo0 |= bit;
        if (v.y + bb >= 0.f) lo1 |= bit;
        if (v.z + bb >= 0.f) lo2 |= bit;
        if (v.w + bb >= 0.f) lo3 |= bit;
    }
#pragma unroll
    for (int c = 32; c < 64; c++) {
        float4 v = *(const float4*)(xp + (size_t)c * HW);
        float bb = sb[c];
        u32 bit = 1u << (c - 32);
        if (v.x + bb >= 0.f) hi0 |= bit;
        if (v.y + bb >= 0.f) hi1 |= bit;
        if (v.z + bb >= 0.f) hi2 |= bit;
        if (v.w + bb >= 0.f) hi3 |= bit;
    }
    u64* op = g_bits1 + (size_t)b * HW + y * NW + sx;
    ulonglong2* ov = (ulonglong2*)op;
    ov[0] = make_ulonglong2(((u64)hi0 << 32) | lo0, ((u64)hi1 << 32) | lo1);
    ov[1] = make_ulonglong2(((u64)hi2 << 32) | lo2, ((u64)hi3 << 32) | lo3);
}

// ---------------------------------------------------------------------------
// Binary 3x3 conv via XOR+POPC, fully fused epilogue.
// Thread = 2 consecutive pixels x all 64 output channels.
// 8 channels of residual prefetched per outer iteration (MLP=8).
// CV==0: residual = x (fp32), out1 (fp16) -> g_out1, bitpack -> g_bits2
// CV==1: residual = g_out1 (fp16, L2-resident), out -> dout (fp32)
// ---------------------------------------------------------------------------
template <int CV>
__global__ void __launch_bounds__(TPB)
bconv_kernel(const float* __restrict__ xin, float* __restrict__ dout,
             const float* __restrict__ bA, const float* __restrict__ sl_,
             const float* __restrict__ bB, const float* __restrict__ bS) {
    __shared__ u64 s_wb[NC][10];      // 80B rows: 16B-aligned per row
    __shared__ int s_corr[NC][9];
    __shared__ float4 s_ep[NC];       // (alpha*scale, bA, slope, bB)
    __shared__ float s_bS[NC];
    int tid = threadIdx.x;
    for (int k = tid; k < NC * 9; k += TPB) {
        int o = k / 9, t = k - o * 9;
        s_wb[o][t] = g_wb[CV][o][t];
        s_corr[o][t] = g_corr[CV][o][t];
    }
    if (tid < NC) {
        s_ep[tid] = make_float4(g_scale[CV][tid] * kALPHA, bA[tid], sl_[tid], bB[tid]);
        s_bS[tid] = (CV == 0) ? bS[tid] : 0.f;
    }
    __syncthreads();

    int seg = blockIdx.x * TPB + tid;
    int b = seg / (NH * SEGROW2);
    int r = seg % (NH * SEGROW2);
    int y = r / SEGROW2;
    int sx = (r % SEGROW2) * 2;
    bool top = (y == 0), bot = (y == NH - 1);
    bool left = (sx == 0), right = (sx + 2 == NW);
    bool border = top | bot | left | right;

    const u64* bitsIn = (CV == 0) ? g_bits1 : g_bits2;

    // activation bit patch: 3 rows x 4 cols covers 2 output pixels; OOB -> 0
    const u64* bp = bitsIn + (size_t)b * HW;
    u64 a[3][4];
#pragma unroll
    for (int rr = 0; rr < 3; rr++) {
        int yy = y - 1 + rr;
        bool rv = (yy >= 0) && (yy < NH);
#pragma unroll
        for (int k = 0; k < 4; k++) {
            int cx = sx - 1 + k;
            a[rr][k] = (rv && cx >= 0 && cx < NW) ? __ldg(bp + yy * NW + cx) : 0ull;
        }
    }

    size_t pixbase = (size_t)b * NC * HW + (size_t)(y * NW + sx);
    const float* rpf = xin + pixbase;           // CV==0 residual (fp32)
    const __half* rph = g_out1 + pixbase;       // CV==1 residual (fp16)
    __half* oph = g_out1 + pixbase;             // CV==0 output (fp16)
    float* opf = dout + pixbase;                // CV==1 output (fp32)

    u32 slo0 = 0, slo1 = 0, shi0 = 0, shi1 = 0;

    // process one channel-pair (o, o+1) with residuals resA/resB (fp32)
    auto do_pair = [&](int o, float2 resA, float2 resB) {
        const ulonglong2* wpA = (const ulonglong2*)&s_wb[o][0];
        const ulonglong2* wpB = (const ulonglong2*)&s_wb[o + 1][0];
        u64 wA[9], wB[9];
        {
            ulonglong2 t0 = wpA[0], t1 = wpA[1], t2 = wpA[2], t3 = wpA[3], t4 = wpA[4];
            wA[0] = t0.x; wA[1] = t0.y; wA[2] = t1.x; wA[3] = t1.y;
            wA[4] = t2.x; wA[5] = t2.y; wA[6] = t3.x; wA[7] = t3.y; wA[8] = t4.x;
        }
        {
            ulonglong2 t0 = wpB[0], t1 = wpB[1], t2 = wpB[2], t3 = wpB[3], t4 = wpB[4];
            wB[0] = t0.x; wB[1] = t0.y; wB[2] = t1.x; wB[3] = t1.y;
            wB[4] = t2.x; wB[5] = t2.y; wB[6] = t3.x; wB[7] = t3.y; wB[8] = t4.x;
        }
        int p0 = 0, p1 = 0, q0 = 0, q1 = 0;
#pragma unroll
        for (int t = 0; t < 9; t++) {
            int rr = t / 3, cc = t - rr * 3;
            u64 a0 = a[rr][cc + 0];
            u64 a1 = a[rr][cc + 1];
            p0 += __popcll(wA[t] ^ a0);
            p1 += __popcll(wA[t] ^ a1);
            q0 += __popcll(wB[t] ^ a0);
            q1 += __popcll(wB[t] ^ a1);
        }
        int cbA = 0, clA = 0, crA = 0, cbB = 0, clB = 0, crB = 0;
        if (border) {
            const int* cA = s_corr[o];
            const int* cB = s_corr[o + 1];
            if (top)  { cbA += cA[0] + cA[1] + cA[2]; cbB += cB[0] + cB[1] + cB[2]; }
            if (bot)  { cbA += cA[6] + cA[7] + cA[8]; cbB += cB[6] + cB[7] + cB[8]; }
            if (left) {
                clA = cA[3] + (top ? 0 : cA[0]) + (bot ? 0 : cA[6]);
                clB = cB[3] + (top ? 0 : cB[0]) + (bot ? 0 : cB[6]);
            }
            if (right) {
                crA = cA[5] + (top ? 0 : cA[2]) + (bot ? 0 : cA[8]);
                crB = cB[5] + (top ? 0 : cB[2]) + (bot ? 0 : cB[8]);
            }
        }
        // channel o
        {
            float4 ep = s_ep[o];
            float v0 = fmaf(ep.x, (float)(576 - 2 * p0 - cbA - clA), resA.x);
            float v1 = fmaf(ep.x, (float)(576 - 2 * p1 - cbA - crA), resA.y);
            v0 += ep.y; v1 += ep.y;
            v0 = fmaxf(v0, 0.f) + ep.z * fminf(v0, 0.f);
            v1 = fmaxf(v1, 0.f) + ep.z * fminf(v1, 0.f);
            v0 += ep.w; v1 += ep.w;
            if (CV == 0) {
                *(half2*)(oph + (size_t)o * HW) = __float22half2_rn(make_float2(v0, v1));
                float bs = s_bS[o];
                u32 bit = 1u << (o & 31);
                if (o < 32) {
                    if (v0 + bs >= 0.f) slo0 |= bit;
                    if (v1 + bs >= 0.f) slo1 |= bit;
                } else {
                    if (v0 + bs >= 0.f) shi0 |= bit;
                    if (v1 + bs >= 0.f) shi1 |= bit;
                }
            } else {
                *(float2*)(opf + (size_t)o * HW) = make_float2(v0, v1);
            }
        }
        // channel o+1
        {
            int o1 = o + 1;
            float4 ep = s_ep[o1];
            float v0 = fmaf(ep.x, (float)(576 - 2 * q0 - cbB - clB), resB.x);
            float v1 = fmaf(ep.x, (float)(576 - 2 * q1 - cbB - crB), resB.y);
            v0 += ep.y; v1 += ep.y;
            v0 = fmaxf(v0, 0.f) + ep.z * fminf(v0, 0.f);
            v1 = fmaxf(v1, 0.f) + ep.z * fminf(v1, 0.f);
            v0 += ep.w; v1 += ep.w;
            if (CV == 0) {
                *(half2*)(oph + (size_t)o1 * HW) = __float22half2_rn(make_float2(v0, v1));
                float bs = s_bS[o1];
                u32 bit = 1u << (o1 & 31);
                if (o1 < 32) {
                    if (v0 + bs >= 0.f) slo0 |= bit;
                    if (v1 + bs >= 0.f) slo1 |= bit;
                } else {
                    if (v0 + bs >= 0.f) shi0 |= bit;
                    if (v1 + bs >= 0.f) shi1 |= bit;
                }
            } else {
                *(float2*)(opf + (size_t)o1 * HW) = make_float2(v0, v1);
            }
        }
    };

    // residual ring: 8 channels in flight, batch-prefetched per outer iter
    if (CV == 0) {
        float2 ring[8], nxt[8];
#pragma unroll
        for (int i = 0; i < 8; i++)
            ring[i] = *(const float2*)(rpf + (size_t)i * HW);
#pragma unroll 1
        for (int o = 0; o < NC; o += 8) {
            int ob = (o + 8 < NC) ? o + 8 : o;
#pragma unroll
            for (int i = 0; i < 8; i++)
                nxt[i] = *(const float2*)(rpf + (size_t)(ob + i) * HW);
#pragma unroll
            for (int pp = 0; pp < 4; pp++)
                do_pair(o + 2 * pp, ring[2 * pp], ring[2 * pp + 1]);
#pragma unroll
            for (int i = 0; i < 8; i++) ring[i] = nxt[i];
        }
    } else {
        half2 ring[8], nxt[8];
#pragma unroll
        for (int i = 0; i < 8; i++)
            ring[i] = *(const half2*)(rph + (size_t)i * HW);
#pragma unroll 1
        for (int o = 0; o < NC; o += 8) {
            int ob = (o + 8 < NC) ? o + 8 : o;
#pragma unroll
            for (int i = 0; i < 8; i++)
                nxt[i] = *(const half2*)(rph + (size_t)(ob + i) * HW);
#pragma unroll
            for (int pp = 0; pp < 4; pp++) {
                float2 rA = __half22float2(ring[2 * pp]);
                float2 rB = __half22float2(ring[2 * pp + 1]);
                do_pair(o + 2 * pp, rA, rB);
            }
#pragma unroll
            for (int i = 0; i < 8; i++) ring[i] = nxt[i];
        }
    }

    if (CV == 0) {
        u64* obp = g_bits2 + (size_t)b * HW + y * NW + sx;
        *(ulonglong2*)obp =
            make_ulonglong2(((u64)shi0 << 32) | slo0, ((u64)shi1 << 32) | slo1);
    }
}

extern "C" void kernel_launch(void* const* d_in, const int* in_sizes, int n_in,
                              void* d_out, int out_size) {
    const float* x   = (const float*)d_in[0];
    const float* w3  = (const float*)d_in[1];
    const float* wpw = (const float*)d_in[2];
    const float* b11 = (const float*)d_in[3];
    const float* b12 = (const float*)d_in[4];
    const float* b13 = (const float*)d_in[5];
    const float* b21 = (const float*)d_in[6];
    const float* b22 = (const float*)d_in[7];
    const float* b23 = (const float*)d_in[8];
    const float* a1  = (const float*)d_in[9];
    const float* a2  = (const float*)d_in[10];
    float* out = (float*)d_out;

    prep_weights_kernel<<<dim3(64, 2), 64>>>(w3, wpw);
    pack_input_kernel<<<NBLK4, TPB>>>(x, b11);
    bconv_kernel<0><<<NBLK2, TPB>>>(x, nullptr, b12, a1, b13, b21);
    bconv_kernel<1><<<NBLK2, TPB>>>(nullptr, out, b22, a2, b23, nullptr);
}

// round 16
// speedup vs baseline: 1.0601x; 1.0596x over previous
#include <cuda_runtime.h>
#include <cuda_fp16.h>

typedef unsigned long long u64;
typedef unsigned int u32;
typedef unsigned short u16;

constexpr int NB = 32, NC = 64, NH = 112, NW = 112;
constexpr int HW = NH * NW;               // 12544
constexpr int SEGROW4 = NW / 4;           // 28 (pack kernel, 4 px/thread)
constexpr int NSEG4 = NB * NH * SEGROW4;  // 100352
constexpr int SEGROW2 = NW / 2;           // 56 (conv kernels, 2 px/thread)
constexpr int NSEG2 = NB * NH * SEGROW2;  // 200704
constexpr int TPB = 128;
constexpr int NBLK4 = NSEG4 / TPB;        // 784
constexpr int NBLKC = NSEG2 / 32;         // 6272 (32 pixel-pairs per block)
constexpr float kALPHA = 0.25f;

// scratch (static device globals; no dynamic allocation)
__device__ u64 g_bits1[NB * HW];
__device__ u64 g_bits2[NB * HW];
__device__ __half g_out1[(size_t)NB * NC * HW];   // fp16: 51.5 MB
__device__ u64 g_wb[2][NC][9];
__device__ int g_corr[2][NC][9];
__device__ float g_scale[2][NC];

// ---------------------------------------------------------------------------
// Weight prep: scale[o]=mean|w|, bit-packed sign words, zero-pad corrections.
// ---------------------------------------------------------------------------
__global__ void prep_weights_kernel(const float* __restrict__ w3,
                                    const float* __restrict__ wpw) {
    int o = blockIdx.x;
    int cv = blockIdx.y;
    const float* w = cv ? wpw : w3;
    int i = threadIdx.x;
    int lane = i & 31, warp = i >> 5;
    const float* wrow = w + (size_t)(o * NC + i) * 9;
    float wv[9];
    float s = 0.f;
#pragma unroll
    for (int t = 0; t < 9; t++) { wv[t] = wrow[t]; s += fabsf(wv[t]); }
    __shared__ u32 sb[2][9];
#pragma unroll
    for (int t = 0; t < 9; t++) {
        u32 m = __ballot_sync(0xffffffffu, wv[t] >= 0.f);
        if (lane == 0) sb[warp][t] = m;
    }
#pragma unroll
    for (int off = 16; off > 0; off >>= 1)
        s += __shfl_down_sync(0xffffffffu, s, off);
    __shared__ float ssum[2];
    if (lane == 0) ssum[warp] = s;
    __syncthreads();
    if (i == 0) g_scale[cv][o] = (ssum[0] + ssum[1]) * (1.0f / 576.0f);
    if (i < 9) {
        u64 wb = ((u64)sb[1][i] << 32) | (u64)sb[0][i];
        g_wb[cv][o][i] = wb;
        g_corr[cv][o][i] = 64 - 2 * __popcll(wb);
    }
}

// ---------------------------------------------------------------------------
// Pack sign(x + b11) into 64-bit channel words. Thread = 4 consecutive pixels.
// ---------------------------------------------------------------------------
__global__ void __launch_bounds__(TPB)
pack_input_kernel(const float* __restrict__ x, const float* __restrict__ b11) {
    __shared__ float sb[NC];
    int tid = threadIdx.x;
    if (tid < NC) sb[tid] = b11[tid];
    __syncthreads();
    int seg = blockIdx.x * TPB + tid;
    int b = seg / (NH * SEGROW4);
    int r = seg % (NH * SEGROW4);
    int y = r / SEGROW4;
    int sx = (r % SEGROW4) * 4;
    const float* xp = x + (size_t)b * NC * HW + y * NW + sx;
    u32 lo0 = 0, lo1 = 0, lo2 = 0, lo3 = 0;
    u32 hi0 = 0, hi1 = 0, hi2 = 0, hi3 = 0;
#pragma unroll
    for (int c = 0; c < 32; c++) {
        float4 v = *(const float4*)(xp + (size_t)c * HW);
        float bb = sb[c];
        u32 bit = 1u << c;
        if (v.x + bb >= 0.f) lo0 |= bit;
        if (v.y + bb >= 0.f) lo1 |= bit;
        if (v.z + bb >= 0.f) lo2 |= bit;
        if (v.w + bb >= 0.f) lo3 |= bit;
    }
#pragma unroll
    for (int c = 32; c < 64; c++) {
        float4 v = *(const float4*)(xp + (size_t)c * HW);
        float bb = sb[c];
        u32 bit = 1u << (c - 32);
        if (v.x + bb >= 0.f) hi0 |= bit;
        if (v.y + bb >= 0.f) hi1 |= bit;
        if (v.z + bb >= 0.f) hi2 |= bit;
        if (v.w + bb >= 0.f) hi3 |= bit;
    }
    u64* op = g_bits1 + (size_t)b * HW + y * NW + sx;
    ulonglong2* ov = (ulonglong2*)op;
    ov[0] = make_ulonglong2(((u64)hi0 << 32) | lo0, ((u64)hi1 << 32) | lo1);
    ov[1] = make_ulonglong2(((u64)hi2 << 32) | lo2, ((u64)hi3 << 32) | lo3);
}

// ---------------------------------------------------------------------------
// Binary 3x3 conv via XOR+POPC, fully fused epilogue.
// Block = 32 consecutive pixel-pairs x all 64 channels.
// Warp q handles channels [16q, 16q+16); lane = pixel-pair.
// Thread = 2 px x 16 channels; residual ring depth 2.
// CV==0: residual = x (fp32), out1 (fp16) -> g_out1, sign bits -> g_bits2 (u16/quarter)
// CV==1: residual = g_out1 (fp16), out -> dout (fp32)
// ---------------------------------------------------------------------------
template <int CV>
__global__ void __launch_bounds__(TPB, 8)
bconv_kernel(const float* __restrict__ xin, float* __restrict__ dout,
             const float* __restrict__ bA, const float* __restrict__ sl_,
             const float* __restrict__ bB, const float* __restrict__ bS) {
    __shared__ u64 s_wb[NC][10];      // 80B rows: 16B-aligned per row
    __shared__ int s_corr[NC][9];
    __shared__ float4 s_ep[NC];       // (alpha*scale, bA, slope, bB)
    __shared__ float s_bS[NC];
    int tid = threadIdx.x;
    for (int k = tid; k < NC * 9; k += TPB) {
        int o = k / 9, t = k - o * 9;
        s_wb[o][t] = g_wb[CV][o][t];
        s_corr[o][t] = g_corr[CV][o][t];
    }
    if (tid < NC) {
        s_ep[tid] = make_float4(g_scale[CV][tid] * kALPHA, bA[tid], sl_[tid], bB[tid]);
        s_bS[tid] = (CV == 0) ? bS[tid] : 0.f;
    }
    __syncthreads();

    int lane = tid & 31;
    int quarter = tid >> 5;          // channel quarter
    int oc0 = quarter * 16;

    int seg = blockIdx.x * 32 + lane;
    int b = seg / (NH * SEGROW2);
    int r = seg % (NH * SEGROW2);
    int y = r / SEGROW2;
    int sx = (r % SEGROW2) * 2;
    bool top = (y == 0), bot = (y == NH - 1);
    bool left = (sx == 0), right = (sx + 2 == NW);
    bool border = top | bot | left | right;

    const u64* bitsIn = (CV == 0) ? g_bits1 : g_bits2;

    // activation bit patch: 3 rows x 4 cols covers 2 output pixels; OOB -> 0
    const u64* bp = bitsIn + (size_t)b * HW;
    u64 a[3][4];
#pragma unroll
    for (int rr = 0; rr < 3; rr++) {
        int yy = y - 1 + rr;
        bool rv = (yy >= 0) && (yy < NH);
#pragma unroll
        for (int k = 0; k < 4; k++) {
            int cx = sx - 1 + k;
            a[rr][k] = (rv && cx >= 0 && cx < NW) ? __ldg(bp + yy * NW + cx) : 0ull;
        }
    }

    size_t pixbase = (size_t)b * NC * HW + (size_t)(y * NW + sx);
    const float* rpf = xin + pixbase;           // CV==0 residual (fp32)
    const __half* rph = g_out1 + pixbase;       // CV==1 residual (fp16)
    __half* oph = g_out1 + pixbase;             // CV==0 output (fp16)
    float* opf = dout + pixbase;                // CV==1 output (fp32)

    u32 sbits0 = 0, sbits1 = 0;     // 16 sign bits per pixel

    // residual ring depth 2 (channels o, o+1 in flight)
    float2 r0, r1;
    if (CV == 0) {
        r0 = *(const float2*)(rpf + (size_t)oc0 * HW);
        r1 = *(const float2*)(rpf + (size_t)(oc0 + 1) * HW);
    } else {
        r0 = __half22float2(*(const half2*)(rph + (size_t)oc0 * HW));
        r1 = __half22float2(*(const half2*)(rph + (size_t)(oc0 + 1) * HW));
    }

#pragma unroll 2
    for (int i = 0; i < 16; i++) {
        int o = oc0 + i;
        // prefetch residual for o+2 (clamped, branch-free)
        int onx = (i < 14) ? o + 2 : o;
        float2 rn;
        if (CV == 0) {
            rn = *(const float2*)(rpf + (size_t)onx * HW);
        } else {
            rn = __half22float2(*(const half2*)(rph + (size_t)onx * HW));
        }

        // weight row: LDS.128 x5 (last reads pad word)
        u64 w[9];
        {
            const ulonglong2* wp = (const ulonglong2*)&s_wb[o][0];
            ulonglong2 t0 = wp[0], t1 = wp[1], t2 = wp[2], t3 = wp[3], t4 = wp[4];
            w[0] = t0.x; w[1] = t0.y; w[2] = t1.x; w[3] = t1.y;
            w[4] = t2.x; w[5] = t2.y; w[6] = t3.x; w[7] = t3.y; w[8] = t4.x;
        }
        int p0 = 0, p1 = 0;
#pragma unroll
        for (int t = 0; t < 9; t++) {
            int rr = t / 3, cc = t - rr * 3;
            p0 += __popcll(w[t] ^ a[rr][cc + 0]);
            p1 += __popcll(w[t] ^ a[rr][cc + 1]);
        }
        int cb = 0, cl = 0, cr = 0;
        if (border) {
            const int* cp = s_corr[o];
            int c0 = cp[0], c1 = cp[1], c2 = cp[2];
            int c3 = cp[3], c5 = cp[5];
            int c6 = cp[6], c7 = cp[7], c8 = cp[8];
            if (top) cb += c0 + c1 + c2;
            if (bot) cb += c6 + c7 + c8;
            if (left)  cl = c3 + (top ? 0 : c0) + (bot ? 0 : c6);
            if (right) cr = c5 + (top ? 0 : c2) + (bot ? 0 : c8);
        }
        float4 ep = s_ep[o];
        float v0 = fmaf(ep.x, (float)(576 - 2 * p0 - cb - cl), r0.x);
        float v1 = fmaf(ep.x, (float)(576 - 2 * p1 - cb - cr), r0.y);
        v0 += ep.y; v1 += ep.y;
        v0 = fmaxf(v0, 0.f) + ep.z * fminf(v0, 0.f);
        v1 = fmaxf(v1, 0.f) + ep.z * fminf(v1, 0.f);
        v0 += ep.w; v1 += ep.w;
        if (CV == 0) {
            *(half2*)(oph + (size_t)o * HW) = __float22half2_rn(make_float2(v0, v1));
            float bs = s_bS[o];
            u32 bit = 1u << i;
            if (v0 + bs >= 0.f) sbits0 |= bit;
            if (v1 + bs >= 0.f) sbits1 |= bit;
        } else {
            *(float2*)(opf + (size_t)o * HW) = make_float2(v0, v1);
        }
        r0 = r1;
        r1 = rn;
    }

    if (CV == 0) {
        // each warp-quarter writes its 16-bit slice of the 64-bit word
        u16* obp = (u16*)g_bits2;
        size_t w0 = (size_t)b * HW + (size_t)y * NW + sx;
        obp[w0 * 4 + quarter] = (u16)sbits0;
        obp[(w0 + 1) * 4 + quarter] = (u16)sbits1;
    }
}

extern "C" void kernel_launch(void* const* d_in, const int* in_sizes, int n_in,
                              void* d_out, int out_size) {
    const float* x   = (const float*)d_in[0];
    const float* w3  = (const float*)d_in[1];
    const float* wpw = (const float*)d_in[2];
    const float* b11 = (const float*)d_in[3];
    const float* b12 = (const float*)d_in[4];
    const float* b13 = (const float*)d_in[5];
    const float* b21 = (const float*)d_in[6];
    const float* b22 = (const float*)d_in[7];
    const float* b23 = (const float*)d_in[8];
    const float* a1  = (const float*)d_in[9];
    const float* a2  = (const float*)d_in[10];
    float* out = (float*)d_out;

    prep_weights_kernel<<<dim3(64, 2), 64>>>(w3, wpw);
    pack_input_kernel<<<NBLK4, TPB>>>(x, b11);
    bconv_kernel<0><<<NBLKC, TPB>>>(x, nullptr, b12, a1, b13, b21);
    bconv_kernel<1><<<NBLKC, TPB>>>(nullptr, out, b22, a2, b23, nullptr);
}